// round 5
// baseline (speedup 1.0000x reference)
#include <cuda_runtime.h>
#include <cuda_bf16.h>
#include <cstdint>

#define Bq   8
#define Lq   1024
#define Eq   512
#define Hq   8
#define HDq  64
#define Pq   2047
#define BLq  8192
#define QKVq 1536
#define SCALEF 0.044194173824159216f  // 1/sqrt(512)

__device__ float g_proj[(size_t)BLq * QKVq];
__device__ float g_pk[(size_t)Pq * Eq];
__device__ float g_ctx[(size_t)BLq * Eq];
__device__ float g_attn_fb[(size_t)Bq * Hq * Lq * Lq];

// ---------------------------------------------------------------------------
// Generic SGEMM: C[M,N] = A[M,K] @ W[N,K]^T (+bias). 128x128 tile, BK=16,
// 256 threads, 8x8 microtile.
// ---------------------------------------------------------------------------
__global__ void __launch_bounds__(256, 2)
gemm128(const float* __restrict__ A, const float* __restrict__ W,
        const float* __restrict__ bias, float* __restrict__ C,
        int M, int N, int K, int lda, int ldw, int ldc)
{
    __shared__ float As[16][132];
    __shared__ float Ws[16][132];
    const int m0 = blockIdx.y * 128, n0 = blockIdx.x * 128;
    const int t  = threadIdx.x;
    const int tx = t & 15, ty = t >> 4;

    float acc[8][8] = {};

    for (int k0 = 0; k0 < K; k0 += 16) {
        #pragma unroll
        for (int i = 0; i < 2; i++) {
            int idx = t + i * 256;
            int row = idx >> 2, kc = (idx & 3) * 4;
            float4 av = make_float4(0.f,0.f,0.f,0.f);
            if (m0 + row < M) av = *(const float4*)(A + (size_t)(m0+row)*lda + k0 + kc);
            As[kc][row]=av.x; As[kc+1][row]=av.y; As[kc+2][row]=av.z; As[kc+3][row]=av.w;
            float4 wv = make_float4(0.f,0.f,0.f,0.f);
            if (n0 + row < N) wv = *(const float4*)(W + (size_t)(n0+row)*ldw + k0 + kc);
            Ws[kc][row]=wv.x; Ws[kc+1][row]=wv.y; Ws[kc+2][row]=wv.z; Ws[kc+3][row]=wv.w;
        }
        __syncthreads();
        #pragma unroll
        for (int kk = 0; kk < 16; kk++) {
            float a[8], b[8];
            *(float4*)(a)   = *(const float4*)&As[kk][ty*8];
            *(float4*)(a+4) = *(const float4*)&As[kk][ty*8+4];
            *(float4*)(b)   = *(const float4*)&Ws[kk][tx*8];
            *(float4*)(b+4) = *(const float4*)&Ws[kk][tx*8+4];
            #pragma unroll
            for (int i = 0; i < 8; i++)
                #pragma unroll
                for (int j = 0; j < 8; j++)
                    acc[i][j] += a[i] * b[j];
        }
        __syncthreads();
    }

    #pragma unroll
    for (int i = 0; i < 8; i++) {
        int row = m0 + ty*8 + i;
        if (row >= M) continue;
        #pragma unroll
        for (int j = 0; j < 8; j += 4) {
            int col = n0 + tx*8 + j;
            float4 r = make_float4(acc[i][j], acc[i][j+1], acc[i][j+2], acc[i][j+3]);
            if (bias) { r.x += bias[col]; r.y += bias[col+1]; r.z += bias[col+2]; r.w += bias[col+3]; }
            *(float4*)(C + (size_t)row*ldc + col) = r;
        }
    }
}

// ---------------------------------------------------------------------------
// Fused score kernel, one plain store per attn element:
//   attn[z,q,k] = (Qu[q] . K[k]) + (Qv[q] . pk[k - q + 1023])
// 128x128 tile; needed pk rows form a 255-row in-range band.
// NOTE: no min-blocks clamp -> ptxas may use up to 255 regs (no spills).
// ---------------------------------------------------------------------------
__global__ void __launch_bounds__(256)
score_fused(const float* __restrict__ ub, const float* __restrict__ vbb,
            float* __restrict__ attn)
{
    const int z = blockIdx.z, b = z >> 3, h = z & 7;
    const int q0 = blockIdx.y * 128, k0 = blockIdx.x * 128;
    const float* Aq = g_proj + (size_t)b*Lq*QKVq + h*192;        // q-part
    const float* Bk = g_proj + (size_t)b*Lq*QKVq + h*192 + 64;   // k-part
    const float* Pk = g_pk + h*64;                               // row stride Eq
    float* Cc = attn + (size_t)z * Lq * Lq;

    const int j0 = k0 - q0 + 896;  // band start in [0, 1792]; rows j0..j0+254

    __shared__ float Su[16][132];
    __shared__ float Sv[16][132];
    __shared__ float Sk[16][132];
    __shared__ float Sp[16][260];   // 255 used; stride 260 => 16B-aligned rows

    const int t  = threadIdx.x;
    const int tx = t & 15, ty = t >> 4;
    const int r0 = tx*8 - ty*8 + 127;   // band row for (i=0, j=0), in [7, 247]

    float acc[8][8] = {};

    for (int d0 = 0; d0 < 64; d0 += 16) {
        #pragma unroll
        for (int i = 0; i < 2; i++) {
            int idx = t + i * 256;
            int row = idx >> 2, kc = (idx & 3) * 4;
            float4 av = *(const float4*)(Aq + (size_t)(q0+row)*QKVq + d0 + kc);
            const float* up = ub  + h*64 + d0 + kc;
            const float* vp = vbb + h*64 + d0 + kc;
            Su[kc][row]   = (av.x + up[0]) * SCALEF;
            Su[kc+1][row] = (av.y + up[1]) * SCALEF;
            Su[kc+2][row] = (av.z + up[2]) * SCALEF;
            Su[kc+3][row] = (av.w + up[3]) * SCALEF;
            Sv[kc][row]   = (av.x + vp[0]) * SCALEF;
            Sv[kc+1][row] = (av.y + vp[1]) * SCALEF;
            Sv[kc+2][row] = (av.z + vp[2]) * SCALEF;
            Sv[kc+3][row] = (av.w + vp[3]) * SCALEF;
            float4 wv = *(const float4*)(Bk + (size_t)(k0+row)*QKVq + d0 + kc);
            Sk[kc][row]=wv.x; Sk[kc+1][row]=wv.y; Sk[kc+2][row]=wv.z; Sk[kc+3][row]=wv.w;
        }
        if (t < 255) {
            const float* pr = Pk + (size_t)(j0 + t) * Eq + d0;
            #pragma unroll
            for (int c = 0; c < 16; c += 4) {
                float4 pv = *(const float4*)(pr + c);
                Sp[c][t] = pv.x; Sp[c+1][t] = pv.y; Sp[c+2][t] = pv.z; Sp[c+3][t] = pv.w;
            }
        }
        __syncthreads();

        #pragma unroll
        for (int kk = 0; kk < 16; kk++) {
            float au[8], av_[8], bk[8], p[16];
            *(float4*)(au)    = *(const float4*)&Su[kk][ty*8];
            *(float4*)(au+4)  = *(const float4*)&Su[kk][ty*8+4];
            *(float4*)(av_)   = *(const float4*)&Sv[kk][ty*8];
            *(float4*)(av_+4) = *(const float4*)&Sv[kk][ty*8+4];
            *(float4*)(bk)    = *(const float4*)&Sk[kk][tx*8];
            *(float4*)(bk+4)  = *(const float4*)&Sk[kk][tx*8+4];
            *(float4*)(p)     = *(const float4*)&Sp[kk][r0-7];
            *(float4*)(p+4)   = *(const float4*)&Sp[kk][r0-3];
            *(float4*)(p+8)   = *(const float4*)&Sp[kk][r0+1];
            *(float4*)(p+12)  = *(const float4*)&Sp[kk][r0+5];
            #pragma unroll
            for (int i = 0; i < 8; i++)
                #pragma unroll
                for (int j = 0; j < 8; j++)
                    acc[i][j] += au[i] * bk[j] + av_[i] * p[7 + j - i];
        }
        __syncthreads();
    }

    #pragma unroll
    for (int i = 0; i < 8; i++) {
        float* rowp = Cc + (size_t)(q0 + ty*8 + i) * Lq + k0 + tx*8;
        #pragma unroll
        for (int j = 0; j < 8; j += 4)
            *(float4*)(rowp + j) = make_float4(acc[i][j], acc[i][j+1],
                                               acc[i][j+2], acc[i][j+3]);
    }
}

// ---------------------------------------------------------------------------
// Row softmax in-place (1024 per row, 256 threads/row).
// ---------------------------------------------------------------------------
__global__ void softmax_kernel(float* __restrict__ attn)
{
    float* row = attn + (size_t)blockIdx.x * Lq;
    const int t = threadIdx.x;
    float4 v = *(reinterpret_cast<float4*>(row) + t);

    float m = fmaxf(fmaxf(v.x, v.y), fmaxf(v.z, v.w));
    #pragma unroll
    for (int o = 16; o > 0; o >>= 1) m = fmaxf(m, __shfl_xor_sync(0xffffffffu, m, o));
    __shared__ float red[8];
    if ((t & 31) == 0) red[t >> 5] = m;
    __syncthreads();
    float bm = red[0];
    #pragma unroll
    for (int i = 1; i < 8; i++) bm = fmaxf(bm, red[i]);

    v.x = expf(v.x - bm); v.y = expf(v.y - bm);
    v.z = expf(v.z - bm); v.w = expf(v.w - bm);
    float s = v.x + v.y + v.z + v.w;
    #pragma unroll
    for (int o = 16; o > 0; o >>= 1) s += __shfl_xor_sync(0xffffffffu, s, o);
    __syncthreads();
    if ((t & 31) == 0) red[t >> 5] = s;
    __syncthreads();
    float bs = red[0];
    #pragma unroll
    for (int i = 1; i < 8; i++) bs += red[i];
    float inv = 1.0f / bs;
    v.x *= inv; v.y *= inv; v.z *= inv; v.w *= inv;
    *(reinterpret_cast<float4*>(row) + t) = v;
}

// ---------------------------------------------------------------------------
// ctx[b,q,h,:] = attn[z] @ V[z].  Per z: 1024x64x1024.
// 256(M) x 64(N) tile, BK=16, 256 threads (32x8), 8x8 microtile.
// ---------------------------------------------------------------------------
__global__ void __launch_bounds__(256)
ctx_gemm(const float* __restrict__ attn)
{
    const int z = blockIdx.z, b = z >> 3, h = z & 7;
    const float* A  = attn  + (size_t)z * Lq * Lq;
    const float* Vm = g_proj + (size_t)b*Lq*QKVq + h*192 + 128;
    float*       Cm = g_ctx  + (size_t)b*Lq*Eq + h*64;

    __shared__ float As[16][260];   // 256 rows, stride 260 (16B-aligned rows)
    __shared__ float Bs[16][68];
    const int m0 = blockIdx.y * 256;
    const int t  = threadIdx.x;
    const int tx = t & 7, ty = t >> 3;    // 8 x 32

    float acc[8][8] = {};

    for (int k0 = 0; k0 < Lq; k0 += 16) {
        #pragma unroll
        for (int i = 0; i < 4; i++) {       // 256 rows x 16 cols / 4-wide = 1024 slots
            int idx = t + i * 256;
            int row = idx >> 2, kc = (idx & 3) * 4;
            float4 av = *(const float4*)(A + (size_t)(m0+row)*Lq + k0 + kc);
            As[kc][row]=av.x; As[kc+1][row]=av.y; As[kc+2][row]=av.z; As[kc+3][row]=av.w;
        }
        {
            int row = t >> 4, c4 = (t & 15) * 4;
            float4 bv = *(const float4*)(Vm + (size_t)(k0+row)*QKVq + c4);
            *(float4*)&Bs[row][c4] = bv;
        }
        __syncthreads();
        #pragma unroll
        for (int kk = 0; kk < 16; kk++) {
            float a[8], bb[8];
            *(float4*)(a)    = *(const float4*)&As[kk][ty*8];
            *(float4*)(a+4)  = *(const float4*)&As[kk][ty*8+4];
            *(float4*)(bb)   = *(const float4*)&Bs[kk][tx*8];
            *(float4*)(bb+4) = *(const float4*)&Bs[kk][tx*8+4];
            #pragma unroll
            for (int i = 0; i < 8; i++)
                #pragma unroll
                for (int j = 0; j < 8; j++)
                    acc[i][j] += a[i] * bb[j];
        }
        __syncthreads();
    }

    #pragma unroll
    for (int i = 0; i < 8; i++) {
        float* cp = Cm + (size_t)(m0 + ty*8 + i)*Eq + tx*8;
        *(float4*)(cp)     = make_float4(acc[i][0], acc[i][1], acc[i][2], acc[i][3]);
        *(float4*)(cp + 4) = make_float4(acc[i][4], acc[i][5], acc[i][6], acc[i][7]);
    }
}

// ---------------------------------------------------------------------------
extern "C" void kernel_launch(void* const* d_in, const int* in_sizes, int n_in,
                              void* d_out, int out_size)
{
    const float* x     = (const float*)d_in[0];
    const float* pos   = (const float*)d_in[1];
    const float* w_in  = (const float*)d_in[2];
    const float* w_pos = (const float*)d_in[3];
    const float* w_out = (const float*)d_in[4];
    const float* b_out = (const float*)d_in[5];
    const float* ub    = (const float*)d_in[6];
    const float* vbb   = (const float*)d_in[7];
    float* out = (float*)d_out;

    float *proj, *pk, *ctx, *attn_fb;
    cudaGetSymbolAddress((void**)&proj,    g_proj);
    cudaGetSymbolAddress((void**)&pk,      g_pk);
    cudaGetSymbolAddress((void**)&ctx,     g_ctx);
    cudaGetSymbolAddress((void**)&attn_fb, g_attn_fb);

    const size_t OUT_E  = (size_t)BLq * Eq;
    const size_t ATTN_E = (size_t)Bq * Hq * Lq * Lq;
    float* attn = ((size_t)out_size >= OUT_E + ATTN_E) ? (out + OUT_E) : attn_fb;

    // 1) QKV projection (8192,1536,512)
    gemm128<<<dim3(QKVq/128, BLq/128), 256>>>(x, w_in, nullptr, proj,
                                              BLq, QKVq, Eq, Eq, Eq, QKVq);
    // 2) positional keys (2047,512,512)
    gemm128<<<dim3(Eq/128, (Pq+127)/128), 256>>>(pos, w_pos, nullptr, pk,
                                                 Pq, Eq, Eq, Eq, Eq, Eq);
    // 3) fused AC + shifted BD logits, single store
    score_fused<<<dim3(Lq/128, Lq/128, Bq*Hq), 256>>>(ub, vbb, attn);
    // 4) softmax
    softmax_kernel<<<Bq*Hq*Lq, 256>>>(attn);
    // 5) ctx = attn @ V  (256-row tiles)
    ctx_gemm<<<dim3(1, Lq/256, Bq*Hq), 256>>>(attn);
    // 6) out projection + bias
    gemm128<<<dim3(Eq/128, BLq/128), 256>>>(ctx, w_out, b_out, out,
                                            BLq, Eq, Eq, Eq, Eq, Eq);
}

// round 6
// speedup vs baseline: 1.1269x; 1.1269x over previous
#include <cuda_runtime.h>
#include <cuda_bf16.h>
#include <cstdint>

#define Bq   8
#define Lq   1024
#define Eq   512
#define Hq   8
#define HDq  64
#define Pq   2047
#define BLq  8192
#define QKVq 1536
#define SCALEF 0.044194173824159216f  // 1/sqrt(512)

__device__ float g_proj[(size_t)BLq * QKVq];
__device__ float g_pk[(size_t)Pq * Eq];
__device__ float g_ctx[(size_t)BLq * Eq];
__device__ float g_attn_fb[(size_t)Bq * Hq * Lq * Lq];

// ---------------------------------------------------------------------------
// Generic SGEMM: C[M,N] = A[M,K] @ W[N,K]^T (+bias). 128x128 tile, BK=16,
// 256 threads, 8x8 microtile.
// ---------------------------------------------------------------------------
__global__ void __launch_bounds__(256, 2)
gemm128(const float* __restrict__ A, const float* __restrict__ W,
        const float* __restrict__ bias, float* __restrict__ C,
        int M, int N, int K, int lda, int ldw, int ldc)
{
    __shared__ float As[16][132];
    __shared__ float Ws[16][132];
    const int m0 = blockIdx.y * 128, n0 = blockIdx.x * 128;
    const int t  = threadIdx.x;
    const int tx = t & 15, ty = t >> 4;

    float acc[8][8] = {};

    for (int k0 = 0; k0 < K; k0 += 16) {
        #pragma unroll
        for (int i = 0; i < 2; i++) {
            int idx = t + i * 256;
            int row = idx >> 2, kc = (idx & 3) * 4;
            float4 av = make_float4(0.f,0.f,0.f,0.f);
            if (m0 + row < M) av = *(const float4*)(A + (size_t)(m0+row)*lda + k0 + kc);
            As[kc][row]=av.x; As[kc+1][row]=av.y; As[kc+2][row]=av.z; As[kc+3][row]=av.w;
            float4 wv = make_float4(0.f,0.f,0.f,0.f);
            if (n0 + row < N) wv = *(const float4*)(W + (size_t)(n0+row)*ldw + k0 + kc);
            Ws[kc][row]=wv.x; Ws[kc+1][row]=wv.y; Ws[kc+2][row]=wv.z; Ws[kc+3][row]=wv.w;
        }
        __syncthreads();
        #pragma unroll
        for (int kk = 0; kk < 16; kk++) {
            float a[8], b[8];
            *(float4*)(a)   = *(const float4*)&As[kk][ty*8];
            *(float4*)(a+4) = *(const float4*)&As[kk][ty*8+4];
            *(float4*)(b)   = *(const float4*)&Ws[kk][tx*8];
            *(float4*)(b+4) = *(const float4*)&Ws[kk][tx*8+4];
            #pragma unroll
            for (int i = 0; i < 8; i++)
                #pragma unroll
                for (int j = 0; j < 8; j++)
                    acc[i][j] += a[i] * b[j];
        }
        __syncthreads();
    }

    #pragma unroll
    for (int i = 0; i < 8; i++) {
        int row = m0 + ty*8 + i;
        if (row >= M) continue;
        #pragma unroll
        for (int j = 0; j < 8; j += 4) {
            int col = n0 + tx*8 + j;
            float4 r = make_float4(acc[i][j], acc[i][j+1], acc[i][j+2], acc[i][j+3]);
            if (bias) { r.x += bias[col]; r.y += bias[col+1]; r.z += bias[col+2]; r.w += bias[col+3]; }
            *(float4*)(C + (size_t)row*ldc + col) = r;
        }
    }
}

// ---------------------------------------------------------------------------
// Fused score kernel:
//   attn[z,q,k] = (Qu[q] . K[k]) + (Qv[q] . pk[k - q + 1023])
// 128x128 tile; pk rows form a 255-row in-range band.
// Two-pass microloop (AC then BD) keeps live regs ~105 -> no spills at occ 2.
// ---------------------------------------------------------------------------
__global__ void __launch_bounds__(256, 2)
score_fused(const float* __restrict__ ub, const float* __restrict__ vbb,
            float* __restrict__ attn)
{
    const int z = blockIdx.z, b = z >> 3, h = z & 7;
    const int q0 = blockIdx.y * 128, k0 = blockIdx.x * 128;
    const float* Aq = g_proj + (size_t)b*Lq*QKVq + h*192;        // q-part
    const float* Bk = g_proj + (size_t)b*Lq*QKVq + h*192 + 64;   // k-part
    const float* Pk = g_pk + h*64;                               // row stride Eq
    float* Cc = attn + (size_t)z * Lq * Lq;

    const int j0 = k0 - q0 + 896;  // band start in [0, 1792]

    __shared__ float Su[16][132];
    __shared__ float Sv[16][132];
    __shared__ float Sk[16][132];
    __shared__ float Sp[16][260];   // 255 used; stride 260 => 16B-aligned rows

    const int t  = threadIdx.x;
    const int tx = t & 15, ty = t >> 4;
    const int r0 = tx*8 - ty*8 + 127;   // band row for (i=0, j=0), in [7, 247]

    float acc[8][8] = {};

    for (int d0 = 0; d0 < 64; d0 += 16) {
        #pragma unroll
        for (int i = 0; i < 2; i++) {
            int idx = t + i * 256;
            int row = idx >> 2, kc = (idx & 3) * 4;
            float4 av = *(const float4*)(Aq + (size_t)(q0+row)*QKVq + d0 + kc);
            const float* up = ub  + h*64 + d0 + kc;
            const float* vp = vbb + h*64 + d0 + kc;
            Su[kc][row]   = (av.x + up[0]) * SCALEF;
            Su[kc+1][row] = (av.y + up[1]) * SCALEF;
            Su[kc+2][row] = (av.z + up[2]) * SCALEF;
            Su[kc+3][row] = (av.w + up[3]) * SCALEF;
            Sv[kc][row]   = (av.x + vp[0]) * SCALEF;
            Sv[kc+1][row] = (av.y + vp[1]) * SCALEF;
            Sv[kc+2][row] = (av.z + vp[2]) * SCALEF;
            Sv[kc+3][row] = (av.w + vp[3]) * SCALEF;
            float4 wv = *(const float4*)(Bk + (size_t)(k0+row)*QKVq + d0 + kc);
            Sk[kc][row]=wv.x; Sk[kc+1][row]=wv.y; Sk[kc+2][row]=wv.z; Sk[kc+3][row]=wv.w;
        }
        if (t < 255) {
            const float* pr = Pk + (size_t)(j0 + t) * Eq + d0;
            #pragma unroll
            for (int c = 0; c < 16; c += 4) {
                float4 pv = *(const float4*)(pr + c);
                Sp[c][t] = pv.x; Sp[c+1][t] = pv.y; Sp[c+2][t] = pv.z; Sp[c+3][t] = pv.w;
            }
        }
        __syncthreads();

        // Pass A: AC contribution (low register pressure)
        #pragma unroll
        for (int kk = 0; kk < 16; kk++) {
            float au[8], bk[8];
            *(float4*)(au)   = *(const float4*)&Su[kk][ty*8];
            *(float4*)(au+4) = *(const float4*)&Su[kk][ty*8+4];
            *(float4*)(bk)   = *(const float4*)&Sk[kk][tx*8];
            *(float4*)(bk+4) = *(const float4*)&Sk[kk][tx*8+4];
            #pragma unroll
            for (int i = 0; i < 8; i++)
                #pragma unroll
                for (int j = 0; j < 8; j++)
                    acc[i][j] += au[i] * bk[j];
        }
        // Pass B: BD (banded) contribution
        #pragma unroll
        for (int kk = 0; kk < 16; kk++) {
            float av_[8], p[16];
            *(float4*)(av_)   = *(const float4*)&Sv[kk][ty*8];
            *(float4*)(av_+4) = *(const float4*)&Sv[kk][ty*8+4];
            *(float4*)(p)     = *(const float4*)&Sp[kk][r0-7];
            *(float4*)(p+4)   = *(const float4*)&Sp[kk][r0-3];
            *(float4*)(p+8)   = *(const float4*)&Sp[kk][r0+1];
            *(float4*)(p+12)  = *(const float4*)&Sp[kk][r0+5];
            #pragma unroll
            for (int i = 0; i < 8; i++)
                #pragma unroll
                for (int j = 0; j < 8; j++)
                    acc[i][j] += av_[i] * p[7 + j - i];
        }
        __syncthreads();
    }

    #pragma unroll
    for (int i = 0; i < 8; i++) {
        float* rowp = Cc + (size_t)(q0 + ty*8 + i) * Lq + k0 + tx*8;
        #pragma unroll
        for (int j = 0; j < 8; j += 4)
            *(float4*)(rowp + j) = make_float4(acc[i][j], acc[i][j+1],
                                               acc[i][j+2], acc[i][j+3]);
    }
}

// ---------------------------------------------------------------------------
// Row softmax in-place (1024 per row, 256 threads/row).
// ---------------------------------------------------------------------------
__global__ void softmax_kernel(float* __restrict__ attn)
{
    float* row = attn + (size_t)blockIdx.x * Lq;
    const int t = threadIdx.x;
    float4 v = *(reinterpret_cast<float4*>(row) + t);

    float m = fmaxf(fmaxf(v.x, v.y), fmaxf(v.z, v.w));
    #pragma unroll
    for (int o = 16; o > 0; o >>= 1) m = fmaxf(m, __shfl_xor_sync(0xffffffffu, m, o));
    __shared__ float red[8];
    if ((t & 31) == 0) red[t >> 5] = m;
    __syncthreads();
    float bm = red[0];
    #pragma unroll
    for (int i = 1; i < 8; i++) bm = fmaxf(bm, red[i]);

    v.x = expf(v.x - bm); v.y = expf(v.y - bm);
    v.z = expf(v.z - bm); v.w = expf(v.w - bm);
    float s = v.x + v.y + v.z + v.w;
    #pragma unroll
    for (int o = 16; o > 0; o >>= 1) s += __shfl_xor_sync(0xffffffffu, s, o);
    __syncthreads();
    if ((t & 31) == 0) red[t >> 5] = s;
    __syncthreads();
    float bs = red[0];
    #pragma unroll
    for (int i = 1; i < 8; i++) bs += red[i];
    float inv = 1.0f / bs;
    v.x *= inv; v.y *= inv; v.z *= inv; v.w *= inv;
    *(reinterpret_cast<float4*>(row) + t) = v;
}

// ---------------------------------------------------------------------------
// ctx[b,q,h,:] = attn[z] @ V[z].  Per z: 1024x64x1024.
// 256(M) x 64(N) tile, BK=16, 256 threads (32x8), 8x8 microtile, occ 2.
// ---------------------------------------------------------------------------
__global__ void __launch_bounds__(256, 2)
ctx_gemm(const float* __restrict__ attn)
{
    const int z = blockIdx.z, b = z >> 3, h = z & 7;
    const float* A  = attn  + (size_t)z * Lq * Lq;
    const float* Vm = g_proj + (size_t)b*Lq*QKVq + h*192 + 128;
    float*       Cm = g_ctx  + (size_t)b*Lq*Eq + h*64;

    __shared__ float As[16][260];   // 256 rows, stride 260 (16B-aligned rows)
    __shared__ float Bs[16][68];
    const int m0 = blockIdx.y * 256;
    const int t  = threadIdx.x;
    const int tx = t & 7, ty = t >> 3;    // 8 x 32

    float acc[8][8] = {};

    for (int k0 = 0; k0 < Lq; k0 += 16) {
        #pragma unroll
        for (int i = 0; i < 4; i++) {
            int idx = t + i * 256;
            int row = idx >> 2, kc = (idx & 3) * 4;
            float4 av = *(const float4*)(A + (size_t)(m0+row)*Lq + k0 + kc);
            As[kc][row]=av.x; As[kc+1][row]=av.y; As[kc+2][row]=av.z; As[kc+3][row]=av.w;
        }
        {
            int row = t >> 4, c4 = (t & 15) * 4;
            float4 bv = *(const float4*)(Vm + (size_t)(k0+row)*QKVq + c4);
            *(float4*)&Bs[row][c4] = bv;
        }
        __syncthreads();
        #pragma unroll
        for (int kk = 0; kk < 16; kk++) {
            float a[8], bb[8];
            *(float4*)(a)    = *(const float4*)&As[kk][ty*8];
            *(float4*)(a+4)  = *(const float4*)&As[kk][ty*8+4];
            *(float4*)(bb)   = *(const float4*)&Bs[kk][tx*8];
            *(float4*)(bb+4) = *(const float4*)&Bs[kk][tx*8+4];
            #pragma unroll
            for (int i = 0; i < 8; i++)
                #pragma unroll
                for (int j = 0; j < 8; j++)
                    acc[i][j] += a[i] * bb[j];
        }
        __syncthreads();
    }

    #pragma unroll
    for (int i = 0; i < 8; i++) {
        float* cp = Cm + (size_t)(m0 + ty*8 + i)*Eq + tx*8;
        *(float4*)(cp)     = make_float4(acc[i][0], acc[i][1], acc[i][2], acc[i][3]);
        *(float4*)(cp + 4) = make_float4(acc[i][4], acc[i][5], acc[i][6], acc[i][7]);
    }
}

// ---------------------------------------------------------------------------
extern "C" void kernel_launch(void* const* d_in, const int* in_sizes, int n_in,
                              void* d_out, int out_size)
{
    const float* x     = (const float*)d_in[0];
    const float* pos   = (const float*)d_in[1];
    const float* w_in  = (const float*)d_in[2];
    const float* w_pos = (const float*)d_in[3];
    const float* w_out = (const float*)d_in[4];
    const float* b_out = (const float*)d_in[5];
    const float* ub    = (const float*)d_in[6];
    const float* vbb   = (const float*)d_in[7];
    float* out = (float*)d_out;

    float *proj, *pk, *ctx, *attn_fb;
    cudaGetSymbolAddress((void**)&proj,    g_proj);
    cudaGetSymbolAddress((void**)&pk,      g_pk);
    cudaGetSymbolAddress((void**)&ctx,     g_ctx);
    cudaGetSymbolAddress((void**)&attn_fb, g_attn_fb);

    const size_t OUT_E  = (size_t)BLq * Eq;
    const size_t ATTN_E = (size_t)Bq * Hq * Lq * Lq;
    float* attn = ((size_t)out_size >= OUT_E + ATTN_E) ? (out + OUT_E) : attn_fb;

    // 1) QKV projection (8192,1536,512)
    gemm128<<<dim3(QKVq/128, BLq/128), 256>>>(x, w_in, nullptr, proj,
                                              BLq, QKVq, Eq, Eq, Eq, QKVq);
    // 2) positional keys (2047,512,512)
    gemm128<<<dim3(Eq/128, (Pq+127)/128), 256>>>(pos, w_pos, nullptr, pk,
                                                 Pq, Eq, Eq, Eq, Eq, Eq);
    // 3) fused AC + shifted BD logits, single store
    score_fused<<<dim3(Lq/128, Lq/128, Bq*Hq), 256>>>(ub, vbb, attn);
    // 4) softmax
    softmax_kernel<<<Bq*Hq*Lq, 256>>>(attn);
    // 5) ctx = attn @ V  (256-row tiles)
    ctx_gemm<<<dim3(1, Lq/256, Bq*Hq), 256>>>(attn);
    // 6) out projection + bias
    gemm128<<<dim3(Eq/128, BLq/128), 256>>>(ctx, w_out, b_out, out,
                                            BLq, Eq, Eq, Eq, Eq, Eq);
}

// round 7
// speedup vs baseline: 1.5057x; 1.3362x over previous
#include <cuda_runtime.h>
#include <cuda_bf16.h>
#include <cstdint>

#define Bq   8
#define Lq   1024
#define Eq   512
#define Hq   8
#define HDq  64
#define Pq   2047
#define BLq  8192
#define QKVq 1536
#define SCALEF 0.044194173824159216f  // 1/sqrt(512)

__device__ float g_proj[(size_t)BLq * QKVq];
__device__ float g_pk[(size_t)Pq * Eq];
__device__ float g_ctx[(size_t)BLq * Eq];
__device__ float g_attn_fb[(size_t)Bq * Hq * Lq * Lq];

__device__ __forceinline__ uint32_t f2tf32(float f) {
    uint32_t u;
    asm("cvt.rna.tf32.f32 %0, %1;" : "=r"(u) : "f"(f));
    return u;
}

__device__ __forceinline__ void mma_tf32(float c[4], const uint32_t a[4],
                                         const uint32_t b[2]) {
    asm volatile(
        "mma.sync.aligned.m16n8k8.row.col.f32.tf32.tf32.f32 "
        "{%0,%1,%2,%3}, {%4,%5,%6,%7}, {%8,%9}, {%0,%1,%2,%3};"
        : "+f"(c[0]), "+f"(c[1]), "+f"(c[2]), "+f"(c[3])
        : "r"(a[0]), "r"(a[1]), "r"(a[2]), "r"(a[3]), "r"(b[0]), "r"(b[1]));
}

// ---------------------------------------------------------------------------
// TF32 tensor-core SGEMM: C[M,N] = A[M,K] @ W[N,K]^T (+bias).
// 128x128 tile, BK=16, 256 threads (8 warps, 2x4), warp tile 64x32.
// smem stride 136 (== 8 mod 32) -> conflict-free fragment gathers.
// ---------------------------------------------------------------------------
__global__ void __launch_bounds__(256, 2)
gemm_tf32(const float* __restrict__ A, const float* __restrict__ W,
          const float* __restrict__ bias, float* __restrict__ C,
          int M, int N, int K, int lda, int ldw, int ldc)
{
    __shared__ uint32_t As[16][136];
    __shared__ uint32_t Bs[16][136];
    const int m0 = blockIdx.y * 128, n0 = blockIdx.x * 128;
    const int t = threadIdx.x, lane = t & 31, warp = t >> 5;
    const int wm = (warp & 1) * 64, wn = (warp >> 1) * 32;
    const int g = lane >> 2, q4 = lane & 3;

    float acc[4][4][4] = {};

    for (int k0 = 0; k0 < K; k0 += 16) {
        #pragma unroll
        for (int i = 0; i < 2; i++) {
            int id = t + i * 256;
            int row = id >> 2, kc = (id & 3) * 4;
            float4 av = make_float4(0.f,0.f,0.f,0.f);
            if (m0 + row < M) av = *(const float4*)(A + (size_t)(m0+row)*lda + k0 + kc);
            As[kc][row] = f2tf32(av.x); As[kc+1][row] = f2tf32(av.y);
            As[kc+2][row] = f2tf32(av.z); As[kc+3][row] = f2tf32(av.w);
            float4 wv = make_float4(0.f,0.f,0.f,0.f);
            if (n0 + row < N) wv = *(const float4*)(W + (size_t)(n0+row)*ldw + k0 + kc);
            Bs[kc][row] = f2tf32(wv.x); Bs[kc+1][row] = f2tf32(wv.y);
            Bs[kc+2][row] = f2tf32(wv.z); Bs[kc+3][row] = f2tf32(wv.w);
        }
        __syncthreads();
        #pragma unroll
        for (int ks = 0; ks < 2; ks++) {
            const int kq = ks * 8;
            uint32_t af[4][4], bf[4][2];
            #pragma unroll
            for (int mi = 0; mi < 4; mi++) {
                int rm = wm + mi * 16;
                af[mi][0] = As[kq + q4][rm + g];
                af[mi][1] = As[kq + q4][rm + 8 + g];
                af[mi][2] = As[kq + 4 + q4][rm + g];
                af[mi][3] = As[kq + 4 + q4][rm + 8 + g];
            }
            #pragma unroll
            for (int ni = 0; ni < 4; ni++) {
                int cn = wn + ni * 8;
                bf[ni][0] = Bs[kq + q4][cn + g];
                bf[ni][1] = Bs[kq + 4 + q4][cn + g];
            }
            #pragma unroll
            for (int mi = 0; mi < 4; mi++)
                #pragma unroll
                for (int ni = 0; ni < 4; ni++)
                    mma_tf32(acc[mi][ni], af[mi], bf[ni]);
        }
        __syncthreads();
    }

    #pragma unroll
    for (int mi = 0; mi < 4; mi++) {
        int row0 = m0 + wm + mi * 16 + g;
        #pragma unroll
        for (int ni = 0; ni < 4; ni++) {
            int col = n0 + wn + ni * 8 + 2 * q4;
            float b0 = bias ? bias[col] : 0.f, b1 = bias ? bias[col+1] : 0.f;
            if (row0 < M)
                *(float2*)(C + (size_t)row0*ldc + col) =
                    make_float2(acc[mi][ni][0] + b0, acc[mi][ni][1] + b1);
            if (row0 + 8 < M)
                *(float2*)(C + (size_t)(row0+8)*ldc + col) =
                    make_float2(acc[mi][ni][2] + b0, acc[mi][ni][3] + b1);
        }
    }
}

// ---------------------------------------------------------------------------
// Fused score kernel (FFMA, two-pass):
//   attn[z,q,k] = (Qu[q] . K[k]) + (Qv[q] . pk[k - q + 1023])
// ---------------------------------------------------------------------------
__global__ void __launch_bounds__(256, 2)
score_fused(const float* __restrict__ ub, const float* __restrict__ vbb,
            float* __restrict__ attn)
{
    const int z = blockIdx.z, b = z >> 3, h = z & 7;
    const int q0 = blockIdx.y * 128, k0 = blockIdx.x * 128;
    const float* Aq = g_proj + (size_t)b*Lq*QKVq + h*192;
    const float* Bk = g_proj + (size_t)b*Lq*QKVq + h*192 + 64;
    const float* Pk = g_pk + h*64;
    float* Cc = attn + (size_t)z * Lq * Lq;

    const int j0 = k0 - q0 + 896;

    __shared__ float Su[16][132];
    __shared__ float Sv[16][132];
    __shared__ float Sk[16][132];
    __shared__ float Sp[16][260];

    const int t  = threadIdx.x;
    const int tx = t & 15, ty = t >> 4;
    const int r0 = tx*8 - ty*8 + 127;

    float acc[8][8] = {};

    for (int d0 = 0; d0 < 64; d0 += 16) {
        #pragma unroll
        for (int i = 0; i < 2; i++) {
            int idx = t + i * 256;
            int row = idx >> 2, kc = (idx & 3) * 4;
            float4 av = *(const float4*)(Aq + (size_t)(q0+row)*QKVq + d0 + kc);
            const float* up = ub  + h*64 + d0 + kc;
            const float* vp = vbb + h*64 + d0 + kc;
            Su[kc][row]   = (av.x + up[0]) * SCALEF;
            Su[kc+1][row] = (av.y + up[1]) * SCALEF;
            Su[kc+2][row] = (av.z + up[2]) * SCALEF;
            Su[kc+3][row] = (av.w + up[3]) * SCALEF;
            Sv[kc][row]   = (av.x + vp[0]) * SCALEF;
            Sv[kc+1][row] = (av.y + vp[1]) * SCALEF;
            Sv[kc+2][row] = (av.z + vp[2]) * SCALEF;
            Sv[kc+3][row] = (av.w + vp[3]) * SCALEF;
            float4 wv = *(const float4*)(Bk + (size_t)(k0+row)*QKVq + d0 + kc);
            Sk[kc][row]=wv.x; Sk[kc+1][row]=wv.y; Sk[kc+2][row]=wv.z; Sk[kc+3][row]=wv.w;
        }
        if (t < 255) {
            const float* pr = Pk + (size_t)(j0 + t) * Eq + d0;
            #pragma unroll
            for (int c = 0; c < 16; c += 4) {
                float4 pv = *(const float4*)(pr + c);
                Sp[c][t] = pv.x; Sp[c+1][t] = pv.y; Sp[c+2][t] = pv.z; Sp[c+3][t] = pv.w;
            }
        }
        __syncthreads();

        #pragma unroll
        for (int kk = 0; kk < 16; kk++) {
            float au[8], bk[8];
            *(float4*)(au)   = *(const float4*)&Su[kk][ty*8];
            *(float4*)(au+4) = *(const float4*)&Su[kk][ty*8+4];
            *(float4*)(bk)   = *(const float4*)&Sk[kk][tx*8];
            *(float4*)(bk+4) = *(const float4*)&Sk[kk][tx*8+4];
            #pragma unroll
            for (int i = 0; i < 8; i++)
                #pragma unroll
                for (int j = 0; j < 8; j++)
                    acc[i][j] += au[i] * bk[j];
        }
        #pragma unroll
        for (int kk = 0; kk < 16; kk++) {
            float av_[8], p[16];
            *(float4*)(av_)   = *(const float4*)&Sv[kk][ty*8];
            *(float4*)(av_+4) = *(const float4*)&Sv[kk][ty*8+4];
            *(float4*)(p)     = *(const float4*)&Sp[kk][r0-7];
            *(float4*)(p+4)   = *(const float4*)&Sp[kk][r0-3];
            *(float4*)(p+8)   = *(const float4*)&Sp[kk][r0+1];
            *(float4*)(p+12)  = *(const float4*)&Sp[kk][r0+5];
            #pragma unroll
            for (int i = 0; i < 8; i++)
                #pragma unroll
                for (int j = 0; j < 8; j++)
                    acc[i][j] += av_[i] * p[7 + j - i];
        }
        __syncthreads();
    }

    #pragma unroll
    for (int i = 0; i < 8; i++) {
        float* rowp = Cc + (size_t)(q0 + ty*8 + i) * Lq + k0 + tx*8;
        #pragma unroll
        for (int j = 0; j < 8; j += 4)
            *(float4*)(rowp + j) = make_float4(acc[i][j], acc[i][j+1],
                                               acc[i][j+2], acc[i][j+3]);
    }
}

// ---------------------------------------------------------------------------
// Row softmax in-place (1024 per row, 256 threads/row).
// ---------------------------------------------------------------------------
__global__ void softmax_kernel(float* __restrict__ attn)
{
    float* row = attn + (size_t)blockIdx.x * Lq;
    const int t = threadIdx.x;
    float4 v = *(reinterpret_cast<float4*>(row) + t);

    float m = fmaxf(fmaxf(v.x, v.y), fmaxf(v.z, v.w));
    #pragma unroll
    for (int o = 16; o > 0; o >>= 1) m = fmaxf(m, __shfl_xor_sync(0xffffffffu, m, o));
    __shared__ float red[8];
    if ((t & 31) == 0) red[t >> 5] = m;
    __syncthreads();
    float bm = red[0];
    #pragma unroll
    for (int i = 1; i < 8; i++) bm = fmaxf(bm, red[i]);

    v.x = expf(v.x - bm); v.y = expf(v.y - bm);
    v.z = expf(v.z - bm); v.w = expf(v.w - bm);
    float s = v.x + v.y + v.z + v.w;
    #pragma unroll
    for (int o = 16; o > 0; o >>= 1) s += __shfl_xor_sync(0xffffffffu, s, o);
    __syncthreads();
    if ((t & 31) == 0) red[t >> 5] = s;
    __syncthreads();
    float bs = red[0];
    #pragma unroll
    for (int i = 1; i < 8; i++) bs += red[i];
    float inv = 1.0f / bs;
    v.x *= inv; v.y *= inv; v.z *= inv; v.w *= inv;
    *(reinterpret_cast<float4*>(row) + t) = v;
}

// ---------------------------------------------------------------------------
// ctx = attn @ V via TF32 mma. Per z: 1024x64x1024.
// 128(M)x64(N) tile, 8 warps (4x2), warp tile 32x32 (2x4 mma tiles).
// ---------------------------------------------------------------------------
__global__ void __launch_bounds__(256, 2)
ctx_tf32(const float* __restrict__ attn)
{
    const int z = blockIdx.z, b = z >> 3, h = z & 7;
    const float* A  = attn  + (size_t)z * Lq * Lq;
    const float* Vm = g_proj + (size_t)b*Lq*QKVq + h*192 + 128;
    float*       Cm = g_ctx  + (size_t)b*Lq*Eq + h*64;

    __shared__ uint32_t As[16][136];
    __shared__ uint32_t Bs[16][72];
    const int m0 = blockIdx.y * 128;
    const int t = threadIdx.x, lane = t & 31, warp = t >> 5;
    const int wm = (warp & 3) * 32, wn = (warp >> 2) * 32;
    const int g = lane >> 2, q4 = lane & 3;

    float acc[2][4][4] = {};

    for (int k0 = 0; k0 < Lq; k0 += 16) {
        #pragma unroll
        for (int i = 0; i < 2; i++) {
            int id = t + i * 256;
            int row = id >> 2, kc = (id & 3) * 4;
            float4 av = *(const float4*)(A + (size_t)(m0+row)*Lq + k0 + kc);
            As[kc][row] = f2tf32(av.x); As[kc+1][row] = f2tf32(av.y);
            As[kc+2][row] = f2tf32(av.z); As[kc+3][row] = f2tf32(av.w);
        }
        {
            int row = t >> 4, c4 = (t & 15) * 4;
            float4 bv = *(const float4*)(Vm + (size_t)(k0+row)*QKVq + c4);
            Bs[row][c4] = f2tf32(bv.x); Bs[row][c4+1] = f2tf32(bv.y);
            Bs[row][c4+2] = f2tf32(bv.z); Bs[row][c4+3] = f2tf32(bv.w);
        }
        __syncthreads();
        #pragma unroll
        for (int ks = 0; ks < 2; ks++) {
            const int kq = ks * 8;
            uint32_t af[2][4], bf[4][2];
            #pragma unroll
            for (int mi = 0; mi < 2; mi++) {
                int rm = wm + mi * 16;
                af[mi][0] = As[kq + q4][rm + g];
                af[mi][1] = As[kq + q4][rm + 8 + g];
                af[mi][2] = As[kq + 4 + q4][rm + g];
                af[mi][3] = As[kq + 4 + q4][rm + 8 + g];
            }
            #pragma unroll
            for (int ni = 0; ni < 4; ni++) {
                int cn = wn + ni * 8;
                bf[ni][0] = Bs[kq + q4][cn + g];
                bf[ni][1] = Bs[kq + 4 + q4][cn + g];
            }
            #pragma unroll
            for (int mi = 0; mi < 2; mi++)
                #pragma unroll
                for (int ni = 0; ni < 4; ni++)
                    mma_tf32(acc[mi][ni], af[mi], bf[ni]);
        }
        __syncthreads();
    }

    #pragma unroll
    for (int mi = 0; mi < 2; mi++) {
        int row0 = m0 + wm + mi * 16 + g;
        #pragma unroll
        for (int ni = 0; ni < 4; ni++) {
            int col = wn + ni * 8 + 2 * q4;
            *(float2*)(Cm + (size_t)row0*Eq + col) =
                make_float2(acc[mi][ni][0], acc[mi][ni][1]);
            *(float2*)(Cm + (size_t)(row0+8)*Eq + col) =
                make_float2(acc[mi][ni][2], acc[mi][ni][3]);
        }
    }
}

// ---------------------------------------------------------------------------
extern "C" void kernel_launch(void* const* d_in, const int* in_sizes, int n_in,
                              void* d_out, int out_size)
{
    const float* x     = (const float*)d_in[0];
    const float* pos   = (const float*)d_in[1];
    const float* w_in  = (const float*)d_in[2];
    const float* w_pos = (const float*)d_in[3];
    const float* w_out = (const float*)d_in[4];
    const float* b_out = (const float*)d_in[5];
    const float* ub    = (const float*)d_in[6];
    const float* vbb   = (const float*)d_in[7];
    float* out = (float*)d_out;

    float *proj, *pk, *ctx, *attn_fb;
    cudaGetSymbolAddress((void**)&proj,    g_proj);
    cudaGetSymbolAddress((void**)&pk,      g_pk);
    cudaGetSymbolAddress((void**)&ctx,     g_ctx);
    cudaGetSymbolAddress((void**)&attn_fb, g_attn_fb);

    const size_t OUT_E  = (size_t)BLq * Eq;
    const size_t ATTN_E = (size_t)Bq * Hq * Lq * Lq;
    float* attn = ((size_t)out_size >= OUT_E + ATTN_E) ? (out + OUT_E) : attn_fb;

    // 1) QKV projection (8192,1536,512) - TF32 tensor cores
    gemm_tf32<<<dim3(QKVq/128, BLq/128), 256>>>(x, w_in, nullptr, proj,
                                                BLq, QKVq, Eq, Eq, Eq, QKVq);
    // 2) positional keys (2047,512,512) - TF32
    gemm_tf32<<<dim3(Eq/128, (Pq+127)/128), 256>>>(pos, w_pos, nullptr, pk,
                                                   Pq, Eq, Eq, Eq, Eq, Eq);
    // 3) fused AC + shifted BD logits (FFMA)
    score_fused<<<dim3(Lq/128, Lq/128, Bq*Hq), 256>>>(ub, vbb, attn);
    // 4) softmax
    softmax_kernel<<<Bq*Hq*Lq, 256>>>(attn);
    // 5) ctx = attn @ V - TF32
    ctx_tf32<<<dim3(1, Lq/128, Bq*Hq), 256>>>(attn);
    // 6) out projection + bias - TF32
    gemm_tf32<<<dim3(Eq/128, BLq/128), 256>>>(ctx, w_out, b_out, out,
                                              BLq, Eq, Eq, Eq, Eq, Eq);
}

// round 8
// speedup vs baseline: 1.7020x; 1.1303x over previous
#include <cuda_runtime.h>
#include <cuda_bf16.h>
#include <cstdint>

#define Bq   8
#define Lq   1024
#define Eq   512
#define Hq   8
#define HDq  64
#define Pq   2047
#define BLq  8192
#define QKVq 1536
#define SCALEF 0.044194173824159216f  // 1/sqrt(512)

__device__ float g_proj[(size_t)BLq * QKVq];
__device__ float g_pk[(size_t)(Pq + 1) * Eq];   // +1 pad row (zero) for band reads
__device__ float g_ctx[(size_t)BLq * Eq];
__device__ float g_attn_fb[(size_t)Bq * Hq * Lq * Lq];

#define SCORE_SMEM (128*260*4 + 2*16*136*4)     // 150528 bytes

__device__ __forceinline__ uint32_t f2tf32(float f) {
    uint32_t u;
    asm("cvt.rna.tf32.f32 %0, %1;" : "=r"(u) : "f"(f));
    return u;
}

__device__ __forceinline__ void mma_tf32(float c[4], const uint32_t a[4],
                                         const uint32_t b[2]) {
    asm volatile(
        "mma.sync.aligned.m16n8k8.row.col.f32.tf32.tf32.f32 "
        "{%0,%1,%2,%3}, {%4,%5,%6,%7}, {%8,%9}, {%0,%1,%2,%3};"
        : "+f"(c[0]), "+f"(c[1]), "+f"(c[2]), "+f"(c[3])
        : "r"(a[0]), "r"(a[1]), "r"(a[2]), "r"(a[3]), "r"(b[0]), "r"(b[1]));
}

// ---------------------------------------------------------------------------
// TF32 tensor-core SGEMM: C[M,N] = A[M,K] @ W[N,K]^T (+bias).
// 128x128 tile, BK=16, 256 threads (8 warps 2x4), warp tile 64x32.
// ---------------------------------------------------------------------------
__global__ void __launch_bounds__(256, 2)
gemm_tf32(const float* __restrict__ A, const float* __restrict__ W,
          const float* __restrict__ bias, float* __restrict__ C,
          int M, int N, int K, int lda, int ldw, int ldc)
{
    __shared__ uint32_t As[16][136];
    __shared__ uint32_t Bs[16][136];
    const int m0 = blockIdx.y * 128, n0 = blockIdx.x * 128;
    const int t = threadIdx.x, lane = t & 31, warp = t >> 5;
    const int wm = (warp & 1) * 64, wn = (warp >> 1) * 32;
    const int g = lane >> 2, q4 = lane & 3;

    float acc[4][4][4] = {};

    for (int k0 = 0; k0 < K; k0 += 16) {
        #pragma unroll
        for (int i = 0; i < 2; i++) {
            int id = t + i * 256;
            int row = id >> 2, kc = (id & 3) * 4;
            float4 av = make_float4(0.f,0.f,0.f,0.f);
            if (m0 + row < M) av = *(const float4*)(A + (size_t)(m0+row)*lda + k0 + kc);
            As[kc][row] = f2tf32(av.x); As[kc+1][row] = f2tf32(av.y);
            As[kc+2][row] = f2tf32(av.z); As[kc+3][row] = f2tf32(av.w);
            float4 wv = make_float4(0.f,0.f,0.f,0.f);
            if (n0 + row < N) wv = *(const float4*)(W + (size_t)(n0+row)*ldw + k0 + kc);
            Bs[kc][row] = f2tf32(wv.x); Bs[kc+1][row] = f2tf32(wv.y);
            Bs[kc+2][row] = f2tf32(wv.z); Bs[kc+3][row] = f2tf32(wv.w);
        }
        __syncthreads();
        #pragma unroll
        for (int ks = 0; ks < 2; ks++) {
            const int kq = ks * 8;
            uint32_t af[4][4], bf[4][2];
            #pragma unroll
            for (int mi = 0; mi < 4; mi++) {
                int rm = wm + mi * 16;
                af[mi][0] = As[kq + q4][rm + g];
                af[mi][1] = As[kq + q4][rm + 8 + g];
                af[mi][2] = As[kq + 4 + q4][rm + g];
                af[mi][3] = As[kq + 4 + q4][rm + 8 + g];
            }
            #pragma unroll
            for (int ni = 0; ni < 4; ni++) {
                int cn = wn + ni * 8;
                bf[ni][0] = Bs[kq + q4][cn + g];
                bf[ni][1] = Bs[kq + 4 + q4][cn + g];
            }
            #pragma unroll
            for (int mi = 0; mi < 4; mi++)
                #pragma unroll
                for (int ni = 0; ni < 4; ni++)
                    mma_tf32(acc[mi][ni], af[mi], bf[ni]);
        }
        __syncthreads();
    }

    #pragma unroll
    for (int mi = 0; mi < 4; mi++) {
        int row0 = m0 + wm + mi * 16 + g;
        #pragma unroll
        for (int ni = 0; ni < 4; ni++) {
            int col = n0 + wn + ni * 8 + 2 * q4;
            float b0 = bias ? bias[col] : 0.f, b1 = bias ? bias[col+1] : 0.f;
            if (row0 < M)
                *(float2*)(C + (size_t)row0*ldc + col) =
                    make_float2(acc[mi][ni][0] + b0, acc[mi][ni][1] + b1);
            if (row0 + 8 < M)
                *(float2*)(C + (size_t)(row0+8)*ldc + col) =
                    make_float2(acc[mi][ni][2] + b0, acc[mi][ni][3] + b1);
        }
    }
}

// ---------------------------------------------------------------------------
// TF32 fused score kernel:
//   attn[z,q,k] = (Qu[q].K[k]) + (Qv[q].pk[k-q+1023])
// BD computed in (q,j) band space via mma (2 chunks of 128 j-cols) into an
// smem band buffer D[128][260]; AC via mma into regs; combine with the
// diagonal shift jloc = c - r + 127 at the epilogue.
// 512 threads (16 warps 4x4), warp tile 32x32, dynamic smem, occ 1.
// ---------------------------------------------------------------------------
__global__ void __launch_bounds__(512)
score_tc(const float* __restrict__ ub, const float* __restrict__ vbb,
         float* __restrict__ attn)
{
    extern __shared__ char sm_raw[];
    float*    D   = (float*)sm_raw;                          // [128][260]
    uint32_t* Aop = (uint32_t*)(sm_raw + 128*260*4);         // [16][136]
    uint32_t* Bop = Aop + 16*136;                            // [16][136]

    const int z = blockIdx.z, b = z >> 3, h = z & 7;
    const int q0 = blockIdx.y * 128, k0 = blockIdx.x * 128;
    const float* Aq = g_proj + (size_t)b*Lq*QKVq + h*192;        // q rows
    const float* Bk = Aq + 64;                                   // k rows
    const float* Pk = g_pk + h*64;                               // stride Eq
    float* Cc = attn + (size_t)z * Lq * Lq;
    const int j0 = k0 - q0 + 896;    // band start in [0,1792]; uses 255(+1 pad) rows

    const int t = threadIdx.x, lane = t & 31, warp = t >> 5;
    const int wm = (warp & 3) * 32, wn = (warp >> 2) * 32;
    const int g = lane >> 2, q4 = lane & 3;
    const int lrow = t >> 2, lkc = (t & 3) * 4;   // loader: 512 thr x float4

    float acc[2][4][4];

    // ---------------- BD phase: D[q][j] over 2 j-chunks ----------------
    #pragma unroll 1
    for (int jc = 0; jc < 2; jc++) {
        #pragma unroll
        for (int mi = 0; mi < 2; mi++)
            #pragma unroll
            for (int ni = 0; ni < 4; ni++)
                #pragma unroll
                for (int e = 0; e < 4; e++) acc[mi][ni][e] = 0.f;

        for (int d0 = 0; d0 < 64; d0 += 16) {
            float4 av = *(const float4*)(Aq + (size_t)(q0+lrow)*QKVq + d0 + lkc);
            const float* vp = vbb + h*64 + d0 + lkc;
            Aop[(lkc+0)*136 + lrow] = f2tf32((av.x + vp[0]) * SCALEF);
            Aop[(lkc+1)*136 + lrow] = f2tf32((av.y + vp[1]) * SCALEF);
            Aop[(lkc+2)*136 + lrow] = f2tf32((av.z + vp[2]) * SCALEF);
            Aop[(lkc+3)*136 + lrow] = f2tf32((av.w + vp[3]) * SCALEF);
            float4 pv = *(const float4*)(Pk + (size_t)(j0 + jc*128 + lrow)*Eq + d0 + lkc);
            Bop[(lkc+0)*136 + lrow] = f2tf32(pv.x);
            Bop[(lkc+1)*136 + lrow] = f2tf32(pv.y);
            Bop[(lkc+2)*136 + lrow] = f2tf32(pv.z);
            Bop[(lkc+3)*136 + lrow] = f2tf32(pv.w);
            __syncthreads();
            #pragma unroll
            for (int ks = 0; ks < 2; ks++) {
                const int kq = ks * 8;
                uint32_t af[2][4], bf[4][2];
                #pragma unroll
                for (int mi = 0; mi < 2; mi++) {
                    int rm = wm + mi * 16;
                    af[mi][0] = Aop[(kq + q4)*136 + rm + g];
                    af[mi][1] = Aop[(kq + q4)*136 + rm + 8 + g];
                    af[mi][2] = Aop[(kq + 4 + q4)*136 + rm + g];
                    af[mi][3] = Aop[(kq + 4 + q4)*136 + rm + 8 + g];
                }
                #pragma unroll
                for (int ni = 0; ni < 4; ni++) {
                    int cn = wn + ni * 8;
                    bf[ni][0] = Bop[(kq + q4)*136 + cn + g];
                    bf[ni][1] = Bop[(kq + 4 + q4)*136 + cn + g];
                }
                #pragma unroll
                for (int mi = 0; mi < 2; mi++)
                    #pragma unroll
                    for (int ni = 0; ni < 4; ni++)
                        mma_tf32(acc[mi][ni], af[mi], bf[ni]);
            }
            __syncthreads();
        }
        // flush chunk to band buffer
        #pragma unroll
        for (int mi = 0; mi < 2; mi++) {
            int row = wm + mi * 16 + g;
            #pragma unroll
            for (int ni = 0; ni < 4; ni++) {
                int col = jc * 128 + wn + ni * 8 + 2 * q4;
                D[row*260 + col]     = acc[mi][ni][0];
                D[row*260 + col + 1] = acc[mi][ni][1];
                D[(row+8)*260 + col]     = acc[mi][ni][2];
                D[(row+8)*260 + col + 1] = acc[mi][ni][3];
            }
        }
    }

    // ---------------- AC phase ----------------
    #pragma unroll
    for (int mi = 0; mi < 2; mi++)
        #pragma unroll
        for (int ni = 0; ni < 4; ni++)
            #pragma unroll
            for (int e = 0; e < 4; e++) acc[mi][ni][e] = 0.f;

    for (int d0 = 0; d0 < 64; d0 += 16) {
        float4 av = *(const float4*)(Aq + (size_t)(q0+lrow)*QKVq + d0 + lkc);
        const float* up = ub + h*64 + d0 + lkc;
        Aop[(lkc+0)*136 + lrow] = f2tf32((av.x + up[0]) * SCALEF);
        Aop[(lkc+1)*136 + lrow] = f2tf32((av.y + up[1]) * SCALEF);
        Aop[(lkc+2)*136 + lrow] = f2tf32((av.z + up[2]) * SCALEF);
        Aop[(lkc+3)*136 + lrow] = f2tf32((av.w + up[3]) * SCALEF);
        float4 kv = *(const float4*)(Bk + (size_t)(k0+lrow)*QKVq + d0 + lkc);
        Bop[(lkc+0)*136 + lrow] = f2tf32(kv.x);
        Bop[(lkc+1)*136 + lrow] = f2tf32(kv.y);
        Bop[(lkc+2)*136 + lrow] = f2tf32(kv.z);
        Bop[(lkc+3)*136 + lrow] = f2tf32(kv.w);
        __syncthreads();
        #pragma unroll
        for (int ks = 0; ks < 2; ks++) {
            const int kq = ks * 8;
            uint32_t af[2][4], bf[4][2];
            #pragma unroll
            for (int mi = 0; mi < 2; mi++) {
                int rm = wm + mi * 16;
                af[mi][0] = Aop[(kq + q4)*136 + rm + g];
                af[mi][1] = Aop[(kq + q4)*136 + rm + 8 + g];
                af[mi][2] = Aop[(kq + 4 + q4)*136 + rm + g];
                af[mi][3] = Aop[(kq + 4 + q4)*136 + rm + 8 + g];
            }
            #pragma unroll
            for (int ni = 0; ni < 4; ni++) {
                int cn = wn + ni * 8;
                bf[ni][0] = Bop[(kq + q4)*136 + cn + g];
                bf[ni][1] = Bop[(kq + 4 + q4)*136 + cn + g];
            }
            #pragma unroll
            for (int mi = 0; mi < 2; mi++)
                #pragma unroll
                for (int ni = 0; ni < 4; ni++)
                    mma_tf32(acc[mi][ni], af[mi], bf[ni]);
        }
        __syncthreads();
    }

    // ---------------- combine AC + shifted BD, store ----------------
    #pragma unroll
    for (int mi = 0; mi < 2; mi++) {
        int row = wm + mi * 16 + g;
        #pragma unroll
        for (int ni = 0; ni < 4; ni++) {
            int c = wn + ni * 8 + 2 * q4;
            int jb = c - row + 127;                 // in [0, 254]
            *(float2*)(Cc + (size_t)(q0+row)*Lq + k0 + c) =
                make_float2(acc[mi][ni][0] + D[row*260 + jb],
                            acc[mi][ni][1] + D[row*260 + jb + 1]);
            int row2 = row + 8, jb2 = jb - 8;       // in [0, 254]
            *(float2*)(Cc + (size_t)(q0+row2)*Lq + k0 + c) =
                make_float2(acc[mi][ni][2] + D[row2*260 + jb2],
                            acc[mi][ni][3] + D[row2*260 + jb2 + 1]);
        }
    }
}

// ---------------------------------------------------------------------------
// Row softmax in-place (1024 per row, 256 threads/row).
// ---------------------------------------------------------------------------
__global__ void softmax_kernel(float* __restrict__ attn)
{
    float* row = attn + (size_t)blockIdx.x * Lq;
    const int t = threadIdx.x;
    float4 v = *(reinterpret_cast<float4*>(row) + t);

    float m = fmaxf(fmaxf(v.x, v.y), fmaxf(v.z, v.w));
    #pragma unroll
    for (int o = 16; o > 0; o >>= 1) m = fmaxf(m, __shfl_xor_sync(0xffffffffu, m, o));
    __shared__ float red[8];
    if ((t & 31) == 0) red[t >> 5] = m;
    __syncthreads();
    float bm = red[0];
    #pragma unroll
    for (int i = 1; i < 8; i++) bm = fmaxf(bm, red[i]);

    v.x = expf(v.x - bm); v.y = expf(v.y - bm);
    v.z = expf(v.z - bm); v.w = expf(v.w - bm);
    float s = v.x + v.y + v.z + v.w;
    #pragma unroll
    for (int o = 16; o > 0; o >>= 1) s += __shfl_xor_sync(0xffffffffu, s, o);
    __syncthreads();
    if ((t & 31) == 0) red[t >> 5] = s;
    __syncthreads();
    float bs = red[0];
    #pragma unroll
    for (int i = 1; i < 8; i++) bs += red[i];
    float inv = 1.0f / bs;
    v.x *= inv; v.y *= inv; v.z *= inv; v.w *= inv;
    *(reinterpret_cast<float4*>(row) + t) = v;
}

// ---------------------------------------------------------------------------
// ctx = attn @ V via TF32 mma. Per z: 1024x64x1024.
// ---------------------------------------------------------------------------
__global__ void __launch_bounds__(256, 2)
ctx_tf32(const float* __restrict__ attn)
{
    const int z = blockIdx.z, b = z >> 3, h = z & 7;
    const float* A  = attn  + (size_t)z * Lq * Lq;
    const float* Vm = g_proj + (size_t)b*Lq*QKVq + h*192 + 128;
    float*       Cm = g_ctx  + (size_t)b*Lq*Eq + h*64;

    __shared__ uint32_t As[16][136];
    __shared__ uint32_t Bs[16][72];
    const int m0 = blockIdx.y * 128;
    const int t = threadIdx.x, lane = t & 31, warp = t >> 5;
    const int wm = (warp & 3) * 32, wn = (warp >> 2) * 32;
    const int g = lane >> 2, q4 = lane & 3;

    float acc[2][4][4] = {};

    for (int k0 = 0; k0 < Lq; k0 += 16) {
        #pragma unroll
        for (int i = 0; i < 2; i++) {
            int id = t + i * 256;
            int row = id >> 2, kc = (id & 3) * 4;
            float4 av = *(const float4*)(A + (size_t)(m0+row)*Lq + k0 + kc);
            As[kc][row] = f2tf32(av.x); As[kc+1][row] = f2tf32(av.y);
            As[kc+2][row] = f2tf32(av.z); As[kc+3][row] = f2tf32(av.w);
        }
        {
            int row = t >> 4, c4 = (t & 15) * 4;
            float4 bv = *(const float4*)(Vm + (size_t)(k0+row)*QKVq + c4);
            Bs[row][c4] = f2tf32(bv.x); Bs[row][c4+1] = f2tf32(bv.y);
            Bs[row][c4+2] = f2tf32(bv.z); Bs[row][c4+3] = f2tf32(bv.w);
        }
        __syncthreads();
        #pragma unroll
        for (int ks = 0; ks < 2; ks++) {
            const int kq = ks * 8;
            uint32_t af[2][4], bf[4][2];
            #pragma unroll
            for (int mi = 0; mi < 2; mi++) {
                int rm = wm + mi * 16;
                af[mi][0] = As[kq + q4][rm + g];
                af[mi][1] = As[kq + q4][rm + 8 + g];
                af[mi][2] = As[kq + 4 + q4][rm + g];
                af[mi][3] = As[kq + 4 + q4][rm + 8 + g];
            }
            #pragma unroll
            for (int ni = 0; ni < 4; ni++) {
                int cn = wn + ni * 8;
                bf[ni][0] = Bs[kq + q4][cn + g];
                bf[ni][1] = Bs[kq + 4 + q4][cn + g];
            }
            #pragma unroll
            for (int mi = 0; mi < 2; mi++)
                #pragma unroll
                for (int ni = 0; ni < 4; ni++)
                    mma_tf32(acc[mi][ni], af[mi], bf[ni]);
        }
        __syncthreads();
    }

    #pragma unroll
    for (int mi = 0; mi < 2; mi++) {
        int row0 = m0 + wm + mi * 16 + g;
        #pragma unroll
        for (int ni = 0; ni < 4; ni++) {
            int col = wn + ni * 8 + 2 * q4;
            *(float2*)(Cm + (size_t)row0*Eq + col) =
                make_float2(acc[mi][ni][0], acc[mi][ni][1]);
            *(float2*)(Cm + (size_t)(row0+8)*Eq + col) =
                make_float2(acc[mi][ni][2], acc[mi][ni][3]);
        }
    }
}

// ---------------------------------------------------------------------------
extern "C" void kernel_launch(void* const* d_in, const int* in_sizes, int n_in,
                              void* d_out, int out_size)
{
    const float* x     = (const float*)d_in[0];
    const float* pos   = (const float*)d_in[1];
    const float* w_in  = (const float*)d_in[2];
    const float* w_pos = (const float*)d_in[3];
    const float* w_out = (const float*)d_in[4];
    const float* b_out = (const float*)d_in[5];
    const float* ub    = (const float*)d_in[6];
    const float* vbb   = (const float*)d_in[7];
    float* out = (float*)d_out;

    float *proj, *pk, *ctx, *attn_fb;
    cudaGetSymbolAddress((void**)&proj,    g_proj);
    cudaGetSymbolAddress((void**)&pk,      g_pk);
    cudaGetSymbolAddress((void**)&ctx,     g_ctx);
    cudaGetSymbolAddress((void**)&attn_fb, g_attn_fb);

    cudaFuncSetAttribute(score_tc, cudaFuncAttributeMaxDynamicSharedMemorySize,
                         SCORE_SMEM);

    const size_t OUT_E  = (size_t)BLq * Eq;
    const size_t ATTN_E = (size_t)Bq * Hq * Lq * Lq;
    float* attn = ((size_t)out_size >= OUT_E + ATTN_E) ? (out + OUT_E) : attn_fb;

    // 1) QKV projection (8192,1536,512) - TF32
    gemm_tf32<<<dim3(QKVq/128, BLq/128), 256>>>(x, w_in, nullptr, proj,
                                                BLq, QKVq, Eq, Eq, Eq, QKVq);
    // 2) positional keys (2047,512,512) - TF32
    gemm_tf32<<<dim3(Eq/128, (Pq+127)/128), 256>>>(pos, w_pos, nullptr, pk,
                                                   Pq, Eq, Eq, Eq, Eq, Eq);
    // 3) fused AC + shifted BD logits - TF32 mma with smem band buffer
    score_tc<<<dim3(Lq/128, Lq/128, Bq*Hq), 512, SCORE_SMEM>>>(ub, vbb, attn);
    // 4) softmax
    softmax_kernel<<<Bq*Hq*Lq, 256>>>(attn);
    // 5) ctx = attn @ V - TF32
    ctx_tf32<<<dim3(1, Lq/128, Bq*Hq), 256>>>(attn);
    // 6) out projection + bias - TF32
    gemm_tf32<<<dim3(Eq/128, BLq/128), 256>>>(ctx, w_out, b_out, out,
                                              BLq, Eq, Eq, Eq, Eq, Eq);
}

// round 9
// speedup vs baseline: 1.8235x; 1.0714x over previous
#include <cuda_runtime.h>
#include <cuda_bf16.h>
#include <cstdint>

#define Bq   8
#define Lq   1024
#define Eq   512
#define Hq   8
#define HDq  64
#define Pq   2047
#define BLq  8192
#define QKVq 1536
#define SCALEF 0.044194173824159216f  // 1/sqrt(512)

__device__ float g_proj[(size_t)BLq * QKVq];
__device__ float g_pk[(size_t)(Pq + 1) * Eq];   // +1 pad row for band reads
__device__ float g_ctx[(size_t)BLq * Eq];
__device__ float g_attn_fb[(size_t)Bq * Hq * Lq * Lq];

// score_tc dynamic smem: D[128][260] + 2 x (A,B) tf32 buffers of 16x136
#define OPSZ  (16*136)
#define SCORE_SMEM (128*260*4 + 4*OPSZ*4)       // 167936 bytes

__device__ __forceinline__ uint32_t f2tf32(float f) {
    uint32_t u;
    asm("cvt.rna.tf32.f32 %0, %1;" : "=r"(u) : "f"(f));
    return u;
}

__device__ __forceinline__ void mma_tf32(float c[4], const uint32_t a[4],
                                         const uint32_t b[2]) {
    asm volatile(
        "mma.sync.aligned.m16n8k8.row.col.f32.tf32.tf32.f32 "
        "{%0,%1,%2,%3}, {%4,%5,%6,%7}, {%8,%9}, {%0,%1,%2,%3};"
        : "+f"(c[0]), "+f"(c[1]), "+f"(c[2]), "+f"(c[3])
        : "r"(a[0]), "r"(a[1]), "r"(a[2]), "r"(a[3]), "r"(b[0]), "r"(b[1]));
}

// ---------------------------------------------------------------------------
// TF32 SGEMM, 2-stage pipelined: C[M,N] = A[M,K] @ W[N,K]^T (+bias).
// 128x128 tile, BK=16, 256 threads (8 warps 2x4), warp tile 64x32.
// ---------------------------------------------------------------------------
__global__ void __launch_bounds__(256, 2)
gemm_tf32(const float* __restrict__ A, const float* __restrict__ W,
          const float* __restrict__ bias, float* __restrict__ C,
          int M, int N, int K, int lda, int ldw, int ldc)
{
    __shared__ uint32_t As[2][16][136];
    __shared__ uint32_t Bs[2][16][136];
    const int m0 = blockIdx.y * 128, n0 = blockIdx.x * 128;
    const int t = threadIdx.x, lane = t & 31, warp = t >> 5;
    const int wm = (warp & 1) * 64, wn = (warp >> 1) * 32;
    const int g = lane >> 2, q4 = lane & 3;
    const int r0 = t >> 2, kc = (t & 3) * 4;   // loader: rows r0, r0+64

    float acc[4][4][4] = {};
    float4 a0, a1, w0, w1;

    auto ldg = [&](int k0) {
        a0 = make_float4(0.f,0.f,0.f,0.f);
        a1 = make_float4(0.f,0.f,0.f,0.f);
        w0 = make_float4(0.f,0.f,0.f,0.f);
        w1 = make_float4(0.f,0.f,0.f,0.f);
        if (m0 + r0      < M) a0 = *(const float4*)(A + (size_t)(m0+r0)*lda + k0 + kc);
        if (m0 + r0 + 64 < M) a1 = *(const float4*)(A + (size_t)(m0+r0+64)*lda + k0 + kc);
        if (n0 + r0      < N) w0 = *(const float4*)(W + (size_t)(n0+r0)*ldw + k0 + kc);
        if (n0 + r0 + 64 < N) w1 = *(const float4*)(W + (size_t)(n0+r0+64)*ldw + k0 + kc);
    };
    auto sts = [&](int buf) {
        As[buf][kc][r0]      = f2tf32(a0.x); As[buf][kc+1][r0]      = f2tf32(a0.y);
        As[buf][kc+2][r0]    = f2tf32(a0.z); As[buf][kc+3][r0]      = f2tf32(a0.w);
        As[buf][kc][r0+64]   = f2tf32(a1.x); As[buf][kc+1][r0+64]   = f2tf32(a1.y);
        As[buf][kc+2][r0+64] = f2tf32(a1.z); As[buf][kc+3][r0+64]   = f2tf32(a1.w);
        Bs[buf][kc][r0]      = f2tf32(w0.x); Bs[buf][kc+1][r0]      = f2tf32(w0.y);
        Bs[buf][kc+2][r0]    = f2tf32(w0.z); Bs[buf][kc+3][r0]      = f2tf32(w0.w);
        Bs[buf][kc][r0+64]   = f2tf32(w1.x); Bs[buf][kc+1][r0+64]   = f2tf32(w1.y);
        Bs[buf][kc+2][r0+64] = f2tf32(w1.z); Bs[buf][kc+3][r0+64]   = f2tf32(w1.w);
    };

    const int nIt = K / 16;
    ldg(0); sts(0);
    __syncthreads();

    for (int it = 0; it < nIt; it++) {
        int buf = it & 1;
        if (it + 1 < nIt) ldg((it + 1) * 16);
        #pragma unroll
        for (int ks = 0; ks < 2; ks++) {
            const int kq = ks * 8;
            uint32_t af[4][4], bf[4][2];
            #pragma unroll
            for (int mi = 0; mi < 4; mi++) {
                int rm = wm + mi * 16;
                af[mi][0] = As[buf][kq + q4][rm + g];
                af[mi][1] = As[buf][kq + q4][rm + 8 + g];
                af[mi][2] = As[buf][kq + 4 + q4][rm + g];
                af[mi][3] = As[buf][kq + 4 + q4][rm + 8 + g];
            }
            #pragma unroll
            for (int ni = 0; ni < 4; ni++) {
                int cn = wn + ni * 8;
                bf[ni][0] = Bs[buf][kq + q4][cn + g];
                bf[ni][1] = Bs[buf][kq + 4 + q4][cn + g];
            }
            #pragma unroll
            for (int mi = 0; mi < 4; mi++)
                #pragma unroll
                for (int ni = 0; ni < 4; ni++)
                    mma_tf32(acc[mi][ni], af[mi], bf[ni]);
        }
        if (it + 1 < nIt) sts(buf ^ 1);
        __syncthreads();
    }

    #pragma unroll
    for (int mi = 0; mi < 4; mi++) {
        int row = m0 + wm + mi * 16 + g;
        #pragma unroll
        for (int ni = 0; ni < 4; ni++) {
            int col = n0 + wn + ni * 8 + 2 * q4;
            float b0 = bias ? bias[col] : 0.f, b1 = bias ? bias[col+1] : 0.f;
            if (row < M)
                *(float2*)(C + (size_t)row*ldc + col) =
                    make_float2(acc[mi][ni][0] + b0, acc[mi][ni][1] + b1);
            if (row + 8 < M)
                *(float2*)(C + (size_t)(row+8)*ldc + col) =
                    make_float2(acc[mi][ni][2] + b0, acc[mi][ni][3] + b1);
        }
    }
}

// ---------------------------------------------------------------------------
// TF32 fused score kernel, pipelined:
//   attn[z,q,k] = (Qu[q].K[k]) + (Qv[q].pk[k-q+1023])
// BD in (q,j) band space (2 chunks of 128 j-cols) -> smem band D[128][260];
// AC into regs; combine with jloc = c - r + 127 at epilogue.
// 512 threads (16 warps 4x4), warp tile 32x32, dynamic smem, occ 1.
// ---------------------------------------------------------------------------
__global__ void __launch_bounds__(512)
score_tc(const float* __restrict__ ub, const float* __restrict__ vbb,
         float* __restrict__ attn)
{
    extern __shared__ char sm_raw[];
    float*    D  = (float*)sm_raw;                     // [128][260]
    uint32_t* OP = (uint32_t*)(sm_raw + 128*260*4);    // 2 x (A,B) buffers

    const int z = blockIdx.z, b = z >> 3, h = z & 7;
    const int q0 = blockIdx.y * 128, k0 = blockIdx.x * 128;
    const float* Aq = g_proj + (size_t)b*Lq*QKVq + h*192;
    const float* Bk = Aq + 64;
    const float* Pk = g_pk + h*64;
    float* Cc = attn + (size_t)z * Lq * Lq;
    const int j0 = k0 - q0 + 896;

    const int t = threadIdx.x, lane = t & 31, warp = t >> 5;
    const int wm = (warp & 3) * 32, wn = (warp >> 2) * 32;
    const int g = lane >> 2, q4 = lane & 3;
    const int lrow = t >> 2, lkc = (t & 3) * 4;

    float acc[2][4][4];
    float4 avr, bvr;

    auto Abuf = [&](int buf) { return OP + buf * 2 * OPSZ; };
    auto Bbuf = [&](int buf) { return OP + buf * 2 * OPSZ + OPSZ; };

    auto sts_a_bias = [&](int buf, const float* biasv, int d0) {
        const float* bp = biasv + h*64 + d0 + lkc;
        uint32_t* Ab = Abuf(buf);
        Ab[(lkc+0)*136 + lrow] = f2tf32((avr.x + bp[0]) * SCALEF);
        Ab[(lkc+1)*136 + lrow] = f2tf32((avr.y + bp[1]) * SCALEF);
        Ab[(lkc+2)*136 + lrow] = f2tf32((avr.z + bp[2]) * SCALEF);
        Ab[(lkc+3)*136 + lrow] = f2tf32((avr.w + bp[3]) * SCALEF);
    };
    auto sts_b = [&](int buf) {
        uint32_t* Bb = Bbuf(buf);
        Bb[(lkc+0)*136 + lrow] = f2tf32(bvr.x);
        Bb[(lkc+1)*136 + lrow] = f2tf32(bvr.y);
        Bb[(lkc+2)*136 + lrow] = f2tf32(bvr.z);
        Bb[(lkc+3)*136 + lrow] = f2tf32(bvr.w);
    };
    auto mma_step = [&](int buf) {
        const uint32_t* Ab = Abuf(buf);
        const uint32_t* Bb = Bbuf(buf);
        #pragma unroll
        for (int ks = 0; ks < 2; ks++) {
            const int kq = ks * 8;
            uint32_t af[2][4], bf[4][2];
            #pragma unroll
            for (int mi = 0; mi < 2; mi++) {
                int rm = wm + mi * 16;
                af[mi][0] = Ab[(kq + q4)*136 + rm + g];
                af[mi][1] = Ab[(kq + q4)*136 + rm + 8 + g];
                af[mi][2] = Ab[(kq + 4 + q4)*136 + rm + g];
                af[mi][3] = Ab[(kq + 4 + q4)*136 + rm + 8 + g];
            }
            #pragma unroll
            for (int ni = 0; ni < 4; ni++) {
                int cn = wn + ni * 8;
                bf[ni][0] = Bb[(kq + q4)*136 + cn + g];
                bf[ni][1] = Bb[(kq + 4 + q4)*136 + cn + g];
            }
            #pragma unroll
            for (int mi = 0; mi < 2; mi++)
                #pragma unroll
                for (int ni = 0; ni < 4; ni++)
                    mma_tf32(acc[mi][ni], af[mi], bf[ni]);
        }
    };
    auto zero_acc = [&]() {
        #pragma unroll
        for (int mi = 0; mi < 2; mi++)
            #pragma unroll
            for (int ni = 0; ni < 4; ni++)
                #pragma unroll
                for (int e = 0; e < 4; e++) acc[mi][ni][e] = 0.f;
    };

    // ---------------- BD phase over 2 j-chunks ----------------
    #pragma unroll 1
    for (int jc = 0; jc < 2; jc++) {
        zero_acc();
        const float* Prow = Pk + (size_t)(j0 + jc*128 + lrow) * Eq;
        avr = *(const float4*)(Aq + (size_t)(q0+lrow)*QKVq + lkc);
        bvr = *(const float4*)(Prow + lkc);
        sts_a_bias(0, vbb, 0); sts_b(0);
        __syncthreads();
        #pragma unroll
        for (int it = 0; it < 4; it++) {
            int buf = it & 1;
            if (it < 3) {
                int d0 = (it + 1) * 16;
                avr = *(const float4*)(Aq + (size_t)(q0+lrow)*QKVq + d0 + lkc);
                bvr = *(const float4*)(Prow + d0 + lkc);
            }
            mma_step(buf);
            if (it < 3) { sts_a_bias(buf ^ 1, vbb, (it + 1) * 16); sts_b(buf ^ 1); }
            __syncthreads();
        }
        #pragma unroll
        for (int mi = 0; mi < 2; mi++) {
            int row = wm + mi * 16 + g;
            #pragma unroll
            for (int ni = 0; ni < 4; ni++) {
                int col = jc * 128 + wn + ni * 8 + 2 * q4;
                D[row*260 + col]         = acc[mi][ni][0];
                D[row*260 + col + 1]     = acc[mi][ni][1];
                D[(row+8)*260 + col]     = acc[mi][ni][2];
                D[(row+8)*260 + col + 1] = acc[mi][ni][3];
            }
        }
    }

    // ---------------- AC phase ----------------
    zero_acc();
    avr = *(const float4*)(Aq + (size_t)(q0+lrow)*QKVq + lkc);
    bvr = *(const float4*)(Bk + (size_t)(k0+lrow)*QKVq + lkc);
    __syncthreads();   // D flush from last BD chunk complete before OP reuse is fine;
                       // this sync orders prior D writes w.r.t. epilogue reads too
    sts_a_bias(0, ub, 0); sts_b(0);
    __syncthreads();
    #pragma unroll
    for (int it = 0; it < 4; it++) {
        int buf = it & 1;
        if (it < 3) {
            int d0 = (it + 1) * 16;
            avr = *(const float4*)(Aq + (size_t)(q0+lrow)*QKVq + d0 + lkc);
            bvr = *(const float4*)(Bk + (size_t)(k0+lrow)*QKVq + d0 + lkc);
        }
        mma_step(buf);
        if (it < 3) { sts_a_bias(buf ^ 1, ub, (it + 1) * 16); sts_b(buf ^ 1); }
        __syncthreads();
    }

    // ---------------- combine AC + shifted BD, store ----------------
    #pragma unroll
    for (int mi = 0; mi < 2; mi++) {
        int row = wm + mi * 16 + g;
        #pragma unroll
        for (int ni = 0; ni < 4; ni++) {
            int c = wn + ni * 8 + 2 * q4;
            int jb = c - row + 127;
            *(float2*)(Cc + (size_t)(q0+row)*Lq + k0 + c) =
                make_float2(acc[mi][ni][0] + D[row*260 + jb],
                            acc[mi][ni][1] + D[row*260 + jb + 1]);
            int row2 = row + 8, jb2 = jb - 8;
            *(float2*)(Cc + (size_t)(q0+row2)*Lq + k0 + c) =
                make_float2(acc[mi][ni][2] + D[row2*260 + jb2],
                            acc[mi][ni][3] + D[row2*260 + jb2 + 1]);
        }
    }
}

// ---------------------------------------------------------------------------
// Row softmax in-place (1024 per row, 256 threads/row).
// ---------------------------------------------------------------------------
__global__ void softmax_kernel(float* __restrict__ attn)
{
    float* row = attn + (size_t)blockIdx.x * Lq;
    const int t = threadIdx.x;
    float4 v = *(reinterpret_cast<float4*>(row) + t);

    float m = fmaxf(fmaxf(v.x, v.y), fmaxf(v.z, v.w));
    #pragma unroll
    for (int o = 16; o > 0; o >>= 1) m = fmaxf(m, __shfl_xor_sync(0xffffffffu, m, o));
    __shared__ float red[8];
    if ((t & 31) == 0) red[t >> 5] = m;
    __syncthreads();
    float bm = red[0];
    #pragma unroll
    for (int i = 1; i < 8; i++) bm = fmaxf(bm, red[i]);

    v.x = expf(v.x - bm); v.y = expf(v.y - bm);
    v.z = expf(v.z - bm); v.w = expf(v.w - bm);
    float s = v.x + v.y + v.z + v.w;
    #pragma unroll
    for (int o = 16; o > 0; o >>= 1) s += __shfl_xor_sync(0xffffffffu, s, o);
    __syncthreads();
    if ((t & 31) == 0) red[t >> 5] = s;
    __syncthreads();
    float bs = red[0];
    #pragma unroll
    for (int i = 1; i < 8; i++) bs += red[i];
    float inv = 1.0f / bs;
    v.x *= inv; v.y *= inv; v.z *= inv; v.w *= inv;
    *(reinterpret_cast<float4*>(row) + t) = v;
}

// ---------------------------------------------------------------------------
// ctx = attn @ V via TF32 mma, pipelined. Per z: 1024x64x1024.
// ---------------------------------------------------------------------------
__global__ void __launch_bounds__(256, 2)
ctx_tf32(const float* __restrict__ attn)
{
    const int z = blockIdx.z, b = z >> 3, h = z & 7;
    const float* A  = attn  + (size_t)z * Lq * Lq;
    const float* Vm = g_proj + (size_t)b*Lq*QKVq + h*192 + 128;
    float*       Cm = g_ctx  + (size_t)b*Lq*Eq + h*64;

    __shared__ uint32_t As[2][16][136];
    __shared__ uint32_t Bs[2][16][72];
    const int m0 = blockIdx.y * 128;
    const int t = threadIdx.x, lane = t & 31, warp = t >> 5;
    const int wm = (warp & 3) * 32, wn = (warp >> 2) * 32;
    const int g = lane >> 2, q4 = lane & 3;
    const int r0 = t >> 2, kc = (t & 3) * 4;   // A loader
    const int br = t >> 4, bc = (t & 15) * 4;  // B loader

    float acc[2][4][4] = {};
    float4 a0r, a1r, bvr;

    auto ldg = [&](int k0) {
        a0r = *(const float4*)(A + (size_t)(m0+r0)*Lq + k0 + kc);
        a1r = *(const float4*)(A + (size_t)(m0+r0+64)*Lq + k0 + kc);
        bvr = *(const float4*)(Vm + (size_t)(k0+br)*QKVq + bc);
    };
    auto sts = [&](int buf) {
        As[buf][kc][r0]      = f2tf32(a0r.x); As[buf][kc+1][r0]      = f2tf32(a0r.y);
        As[buf][kc+2][r0]    = f2tf32(a0r.z); As[buf][kc+3][r0]      = f2tf32(a0r.w);
        As[buf][kc][r0+64]   = f2tf32(a1r.x); As[buf][kc+1][r0+64]   = f2tf32(a1r.y);
        As[buf][kc+2][r0+64] = f2tf32(a1r.z); As[buf][kc+3][r0+64]   = f2tf32(a1r.w);
        Bs[buf][br][bc]   = f2tf32(bvr.x); Bs[buf][br][bc+1] = f2tf32(bvr.y);
        Bs[buf][br][bc+2] = f2tf32(bvr.z); Bs[buf][br][bc+3] = f2tf32(bvr.w);
    };

    ldg(0); sts(0);
    __syncthreads();

    for (int it = 0; it < 64; it++) {
        int buf = it & 1;
        if (it + 1 < 64) ldg((it + 1) * 16);
        #pragma unroll
        for (int ks = 0; ks < 2; ks++) {
            const int kq = ks * 8;
            uint32_t af[2][4], bf[4][2];
            #pragma unroll
            for (int mi = 0; mi < 2; mi++) {
                int rm = wm + mi * 16;
                af[mi][0] = As[buf][kq + q4][rm + g];
                af[mi][1] = As[buf][kq + q4][rm + 8 + g];
                af[mi][2] = As[buf][kq + 4 + q4][rm + g];
                af[mi][3] = As[buf][kq + 4 + q4][rm + 8 + g];
            }
            #pragma unroll
            for (int ni = 0; ni < 4; ni++) {
                int cn = wn + ni * 8;
                bf[ni][0] = Bs[buf][kq + q4][cn + g];
                bf[ni][1] = Bs[buf][kq + 4 + q4][cn + g];
            }
            #pragma unroll
            for (int mi = 0; mi < 2; mi++)
                #pragma unroll
                for (int ni = 0; ni < 4; ni++)
                    mma_tf32(acc[mi][ni], af[mi], bf[ni]);
        }
        if (it + 1 < 64) sts(buf ^ 1);
        __syncthreads();
    }

    #pragma unroll
    for (int mi = 0; mi < 2; mi++) {
        int row0 = m0 + wm + mi * 16 + g;
        #pragma unroll
        for (int ni = 0; ni < 4; ni++) {
            int col = wn + ni * 8 + 2 * q4;
            *(float2*)(Cm + (size_t)row0*Eq + col) =
                make_float2(acc[mi][ni][0], acc[mi][ni][1]);
            *(float2*)(Cm + (size_t)(row0+8)*Eq + col) =
                make_float2(acc[mi][ni][2], acc[mi][ni][3]);
        }
    }
}

// ---------------------------------------------------------------------------
extern "C" void kernel_launch(void* const* d_in, const int* in_sizes, int n_in,
                              void* d_out, int out_size)
{
    const float* x     = (const float*)d_in[0];
    const float* pos   = (const float*)d_in[1];
    const float* w_in  = (const float*)d_in[2];
    const float* w_pos = (const float*)d_in[3];
    const float* w_out = (const float*)d_in[4];
    const float* b_out = (const float*)d_in[5];
    const float* ub    = (const float*)d_in[6];
    const float* vbb   = (const float*)d_in[7];
    float* out = (float*)d_out;

    float *proj, *pk, *ctx, *attn_fb;
    cudaGetSymbolAddress((void**)&proj,    g_proj);
    cudaGetSymbolAddress((void**)&pk,      g_pk);
    cudaGetSymbolAddress((void**)&ctx,     g_ctx);
    cudaGetSymbolAddress((void**)&attn_fb, g_attn_fb);

    cudaFuncSetAttribute(score_tc, cudaFuncAttributeMaxDynamicSharedMemorySize,
                         SCORE_SMEM);

    const size_t OUT_E  = (size_t)BLq * Eq;
    const size_t ATTN_E = (size_t)Bq * Hq * Lq * Lq;
    float* attn = ((size_t)out_size >= OUT_E + ATTN_E) ? (out + OUT_E) : attn_fb;

    // 1) QKV projection (8192,1536,512) - TF32
    gemm_tf32<<<dim3(QKVq/128, BLq/128), 256>>>(x, w_in, nullptr, proj,
                                                BLq, QKVq, Eq, Eq, Eq, QKVq);
    // 2) positional keys (2047,512,512) - TF32
    gemm_tf32<<<dim3(Eq/128, (Pq+127)/128), 256>>>(pos, w_pos, nullptr, pk,
                                                   Pq, Eq, Eq, Eq, Eq, Eq);
    // 3) fused AC + shifted BD logits - TF32, pipelined
    score_tc<<<dim3(Lq/128, Lq/128, Bq*Hq), 512, SCORE_SMEM>>>(ub, vbb, attn);
    // 4) softmax
    softmax_kernel<<<Bq*Hq*Lq, 256>>>(attn);
    // 5) ctx = attn @ V - TF32, pipelined
    ctx_tf32<<<dim3(1, Lq/128, Bq*Hq), 256>>>(attn);
    // 6) out projection + bias - TF32
    gemm_tf32<<<dim3(Eq/128, BLq/128), 256>>>(ctx, w_out, b_out, out,
                                              BLq, Eq, Eq, Eq, Eq, Eq);
}